// round 3
// baseline (speedup 1.0000x reference)
#include <cuda_runtime.h>

// Scratch for the j-reduced weight matrix Wsum[m][k] = sum_j W[j][m][k].
__device__ float g_wsum[256 * 256];

// ---------------------------------------------------------------------------
// Kernel A: Wsum[m,k] = sum_j W[j,m,k]
// W is [256, 256, 256] fp32 (j slowest). We treat the trailing (m,k) plane as
// 16384 float4 columns. Block = 256 threads = 64 float4-columns x 4 j-groups;
// each group sums 64 j-slices, then a deterministic shared combine.
// Grid = 256 blocks covers all 16384 columns. Reads 64 MB, writes 256 KB.
// ---------------------------------------------------------------------------
__global__ void __launch_bounds__(256) wsum_kernel(const float* __restrict__ W) {
    const int lane = threadIdx.x & 63;   // float4 column within block
    const int jg   = threadIdx.x >> 6;   // j-group 0..3
    const int col  = blockIdx.x * 64 + lane;  // global float4 column 0..16383

    const float4* __restrict__ W4 = (const float4*)W;
    float4 acc = make_float4(0.f, 0.f, 0.f, 0.f);
    const int j0 = jg * 64;
#pragma unroll 8
    for (int j = 0; j < 64; ++j) {
        float4 w = W4[(size_t)(j0 + j) * 16384 + col];
        acc.x += w.x; acc.y += w.y; acc.z += w.z; acc.w += w.w;
    }

    __shared__ float4 sh[256];
    sh[threadIdx.x] = acc;
    __syncthreads();

    if (jg == 0) {
        float4 a = sh[lane];
        float4 b = sh[64 + lane];
        float4 c = sh[128 + lane];
        float4 d = sh[192 + lane];
        float4 r;
        r.x = (a.x + b.x) + (c.x + d.x);
        r.y = (a.y + b.y) + (c.y + d.y);
        r.z = (a.z + b.z) + (c.z + d.z);
        r.w = (a.w + b.w) + (c.w + d.w);
        ((float4*)g_wsum)[col] = r;
    }
}

// ---------------------------------------------------------------------------
// Kernel B: per batch row b (512 blocks, 256 threads):
//   s[k]   = sum_m inputs[b,m] * Wsum[m,k]     (Wsum L2-resident, 256 KB)
//   v[k]   = s[k] / 256
//   s2     = sum_k v[k]^2                       (block reduction)
//   o[k]   = (s2/(1+s2)/sqrt(s2+1e-7)) * v[k]
//   out[b,i,k] = o[k]  for all i                (broadcast, float4 stores)
// Writes 128 MB total -> dominant cost.
// ---------------------------------------------------------------------------
__global__ void __launch_bounds__(256) routing_kernel(const float* __restrict__ inputs,
                                                      float* __restrict__ out) {
    const int b = blockIdx.x;
    const int t = threadIdx.x;  // 0..255, t == k

    __shared__ float in_sh[256];
    __shared__ float red[8];
    __shared__ float o_sh[256];

    in_sh[t] = inputs[b * 256 + t];
    __syncthreads();

    float acc = 0.f;
#pragma unroll 8
    for (int m = 0; m < 256; ++m)
        acc = fmaf(in_sh[m], g_wsum[m * 256 + t], acc);

    const float v = acc * (1.0f / 256.0f);

    // block-wide sum of v^2 (deterministic: warp shuffles + fixed combine)
    float sq = v * v;
#pragma unroll
    for (int o = 16; o > 0; o >>= 1)
        sq += __shfl_xor_sync(0xffffffffu, sq, o);
    if ((t & 31) == 0) red[t >> 5] = sq;
    __syncthreads();

    const float s2 = ((red[0] + red[1]) + (red[2] + red[3])) +
                     ((red[4] + red[5]) + (red[6] + red[7]));
    const float scale = s2 / (1.0f + s2) / sqrtf(s2 + 1e-7f);

    o_sh[t] = scale * v;
    __syncthreads();

    // Broadcast write: out[b][i][k] = o[k]; 16384 float4 stores per block.
    const float4 o4 = ((const float4*)o_sh)[t & 63];
    float4* __restrict__ out4 = (float4*)out + (size_t)b * 16384;
    const int row0 = t >> 6;       // 0..3
    const int col4 = t & 63;       // 0..63
#pragma unroll 8
    for (int it = 0; it < 64; ++it) {
        out4[(size_t)(it * 4 + row0) * 64 + col4] = o4;
    }
}

extern "C" void kernel_launch(void* const* d_in, const int* in_sizes, int n_in,
                              void* d_out, int out_size) {
    const float* inputs = (const float*)d_in[0];  // [512, 256]
    const float* W      = (const float*)d_in[1];  // [256, 256, 256]
    // Robustness: identify by element count (inputs=131072, W=16777216).
    if (n_in >= 2 && in_sizes[0] > in_sizes[1]) {
        const float* tmp = inputs; inputs = W; W = tmp;
    }
    float* out = (float*)d_out;  // [512, 256, 256]

    wsum_kernel<<<256, 256>>>(W);
    routing_kernel<<<512, 256>>>(inputs, out);
    (void)out_size;
}